// round 5
// baseline (speedup 1.0000x reference)
#include <cuda_runtime.h>
#include <math.h>
#include <stdint.h>

#define N_NODES 50000
#define IN_DIM  27
#define F1      256
#define H1      4
#define F2      128
#define H2      2

// ---------------- scratch (no allocations allowed) ----------------
__device__ float g_h1  [N_NODES * F1];
__device__ float g_agg1[N_NODES * F1];
__device__ float g_h2  [N_NODES * F2];
__device__ float g_agg2[N_NODES * F2];
__device__ float g_ss  [N_NODES * H1];
__device__ float g_sd  [N_NODES * H1];
__device__ float g_z   [N_NODES * H1];

__device__ __forceinline__ void red_add_f4(float* p, float4 v) {
    asm volatile("red.global.add.v4.f32 [%0], {%1, %2, %3, %4};"
                 :: "l"(p), "f"(v.x), "f"(v.y), "f"(v.z), "f"(v.w) : "memory");
}

__device__ __forceinline__ uint32_t f2tf32(float x) {
    uint32_t r;
    asm("cvt.rna.tf32.f32 %0, %1;" : "=r"(r) : "f"(x));
    return r;
}

// ---------------- GEMM1: x[N,27] @ W1[27,256] -> h1[N,256] ----------------
__global__ void gemm1_kernel(const float* __restrict__ x,
                             const float* __restrict__ W,
                             float* __restrict__ out) {
    __shared__ float Ws[IN_DIM * F1];
    __shared__ float xs[64 * IN_DIM];
    int t = threadIdx.x;                // 256 threads
    for (int i = t; i < IN_DIM * F1; i += 256) Ws[i] = W[i];
    int r0 = blockIdx.x * 64;
    for (int i = t; i < 64 * IN_DIM; i += 256) {
        int r = i / IN_DIM, c = i % IN_DIM;
        int gr = r0 + r;
        xs[i] = (gr < N_NODES) ? x[gr * IN_DIM + c] : 0.f;
    }
    __syncthreads();
    float w[IN_DIM];
#pragma unroll
    for (int k = 0; k < IN_DIM; k++) w[k] = Ws[k * F1 + t];
    for (int r = 0; r < 64; r++) {
        int gr = r0 + r;
        if (gr >= N_NODES) break;
        float acc = 0.f;
#pragma unroll
        for (int k = 0; k < IN_DIM; k++) acc += xs[r * IN_DIM + k] * w[k];
        out[(size_t)gr * F1 + t] = acc;
    }
}

// ---------------- per-node attention half-scores ----------------
template<int H>
__global__ void scores_kernel(const float* __restrict__ h,
                              const float* __restrict__ asrc,
                              const float* __restrict__ adst,
                              float* __restrict__ ss, float* __restrict__ sd) {
    int gid  = blockIdx.x * blockDim.x + threadIdx.x;
    int warp = gid >> 5, lane = gid & 31;
    if (warp >= N_NODES * H) return;
    int n = warp / H, hh = warp % H;
    const float* hp = h + (size_t)n * (H * 64) + hh * 64;
    const float* as = asrc + hh * 64;
    const float* ad = adst + hh * 64;
    float v0 = hp[lane], v1 = hp[lane + 32];
    float s1 = v0 * as[lane] + v1 * as[lane + 32];
    float s2 = v0 * ad[lane] + v1 * ad[lane + 32];
#pragma unroll
    for (int o = 16; o > 0; o >>= 1) {
        s1 += __shfl_down_sync(0xffffffffu, s1, o);
        s2 += __shfl_down_sync(0xffffffffu, s2, o);
    }
    if (lane == 0) { ss[warp] = s1; sd[warp] = s2; }
}

// ---------------- edge pass: z += e ; agg += e * h[src] (no max subtraction;
// softmax is shift-invariant and logits are small) ----------------
template<int H, int F>
__global__ void edge_agg_kernel(const int* __restrict__ ei, int E, int ET,
                                const float* __restrict__ ss,
                                const float* __restrict__ sd,
                                float* __restrict__ z,
                                const float* __restrict__ h,
                                float* __restrict__ agg) {
    int gid = blockIdx.x * blockDim.x + threadIdx.x;
    int e = gid >> 5, lane = gid & 31;
    if (e >= ET) return;
    int src, dst;
    if (e < E) { src = ei[e]; dst = ei[E + e]; }
    else       { src = dst = e - E; }
    float ev = 0.f;
    if (lane < H) {
        float l = ss[src * H + lane] + sd[dst * H + lane];
        l = (l > 0.f) ? l : 0.2f * l;
        ev = __expf(l);
        atomicAdd(&z[dst * H + lane], ev);
    }
    const float4* hs = (const float4*)(h + (size_t)src * F);
    float* ag = agg + (size_t)dst * F;
#pragma unroll
    for (int i = 0; i < F / 128; i++) {
        int f = lane + i * 32;                            // float4 index; col = 4f
        float evc = __shfl_sync(0xffffffffu, ev, f >> 4); // head = 4f/64 = f>>4
        float4 v = hs[f];
        v.x *= evc; v.y *= evc; v.z *= evc; v.w *= evc;
        red_add_f4(ag + f * 4, v);
    }
}

// ---------------- finalize: normalize by z, add bias, elu (in place) ----------------
template<int H, int F>
__global__ void finalize_kernel(float* __restrict__ agg,
                                const float* __restrict__ z,
                                const float* __restrict__ b) {
    int i = blockIdx.x * blockDim.x + threadIdx.x;
    if (i >= N_NODES * F) return;
    int c = i % F, n = i / F;
    int hh = c >> 6;
    float v = agg[i] / (z[n * H + hh] + 1e-16f) + b[c];
    agg[i] = (v > 0.f) ? v : expm1f(v);
}

// ---------------- GEMM2 (tf32 tensor cores): A[M,256] @ B[256,128] -> C[M,128]
// 128x128 block tile, 8 warps, each warp 32x64, mma.m16n8k8.tf32 ----------------
__global__ void gemm2_tf32_kernel(const float* __restrict__ A,
                                  const float* __restrict__ B,
                                  float* __restrict__ C) {
    __shared__ uint32_t As[128][36];   // [m][k], pad 36 -> conflict-free
    __shared__ uint32_t Bs[32][132];   // [k][n], pad 132 -> conflict-free
    int t = threadIdx.x;               // 256 threads = 8 warps
    int lane = t & 31, warp = t >> 5;
    int g = lane >> 2, tig = lane & 3;
    int wm = warp >> 1, wn = warp & 1; // 4 x 2 warp grid
    int row0 = blockIdx.x * 128;

    float acc[2][8][4];
#pragma unroll
    for (int mt = 0; mt < 2; mt++)
#pragma unroll
        for (int nt = 0; nt < 8; nt++)
#pragma unroll
            for (int j = 0; j < 4; j++) acc[mt][nt][j] = 0.f;

    for (int kt = 0; kt < 256; kt += 32) {
        // load A tile 128x32 (1024 float4 by 256 threads)
#pragma unroll
        for (int s = 0; s < 4; s++) {
            int i = t + s * 256;       // [0,1024)
            int r = i >> 3, kq = i & 7;
            int gr = row0 + r;
            float4 v = make_float4(0.f, 0.f, 0.f, 0.f);
            if (gr < N_NODES) v = *(const float4*)&A[(size_t)gr * 256 + kt + kq * 4];
            As[r][kq * 4 + 0] = f2tf32(v.x);
            As[r][kq * 4 + 1] = f2tf32(v.y);
            As[r][kq * 4 + 2] = f2tf32(v.z);
            As[r][kq * 4 + 3] = f2tf32(v.w);
        }
        // load B tile 32x128
#pragma unroll
        for (int s = 0; s < 4; s++) {
            int i = t + s * 256;       // [0,1024)
            int k = i >> 5, cq = i & 31;
            float4 v = *(const float4*)&B[(size_t)(kt + k) * 128 + cq * 4];
            Bs[k][cq * 4 + 0] = f2tf32(v.x);
            Bs[k][cq * 4 + 1] = f2tf32(v.y);
            Bs[k][cq * 4 + 2] = f2tf32(v.z);
            Bs[k][cq * 4 + 3] = f2tf32(v.w);
        }
        __syncthreads();

#pragma unroll
        for (int k8 = 0; k8 < 32; k8 += 8) {
            uint32_t af[2][4];
#pragma unroll
            for (int mt = 0; mt < 2; mt++) {
                int mrow = wm * 32 + mt * 16;
                af[mt][0] = As[mrow + g    ][k8 + tig];
                af[mt][1] = As[mrow + g + 8][k8 + tig];
                af[mt][2] = As[mrow + g    ][k8 + tig + 4];
                af[mt][3] = As[mrow + g + 8][k8 + tig + 4];
            }
            uint32_t bf[8][2];
#pragma unroll
            for (int nt = 0; nt < 8; nt++) {
                int ncol = wn * 64 + nt * 8;
                bf[nt][0] = Bs[k8 + tig    ][ncol + g];
                bf[nt][1] = Bs[k8 + tig + 4][ncol + g];
            }
#pragma unroll
            for (int mt = 0; mt < 2; mt++)
#pragma unroll
                for (int nt = 0; nt < 8; nt++) {
                    asm volatile(
                        "mma.sync.aligned.m16n8k8.row.col.f32.tf32.tf32.f32 "
                        "{%0,%1,%2,%3}, {%4,%5,%6,%7}, {%8,%9}, {%0,%1,%2,%3};"
                        : "+f"(acc[mt][nt][0]), "+f"(acc[mt][nt][1]),
                          "+f"(acc[mt][nt][2]), "+f"(acc[mt][nt][3])
                        : "r"(af[mt][0]), "r"(af[mt][1]), "r"(af[mt][2]), "r"(af[mt][3]),
                          "r"(bf[nt][0]), "r"(bf[nt][1]));
                }
        }
        __syncthreads();
    }

    // write back
#pragma unroll
    for (int mt = 0; mt < 2; mt++) {
#pragma unroll
        for (int nt = 0; nt < 8; nt++) {
            int col = wn * 64 + nt * 8 + 2 * tig;
            int r1 = row0 + wm * 32 + mt * 16 + g;
            int r2 = r1 + 8;
            if (r1 < N_NODES)
                *(float2*)&C[(size_t)r1 * 128 + col] =
                    make_float2(acc[mt][nt][0], acc[mt][nt][1]);
            if (r2 < N_NODES)
                *(float2*)&C[(size_t)r2 * 128 + col] =
                    make_float2(acc[mt][nt][2], acc[mt][nt][3]);
        }
    }
}

// ---------------- final: sigmoid(h[N,128] @ Wfc[128,1] + bfc) ----------------
__global__ void out_kernel(const float* __restrict__ h,
                           const float* __restrict__ Wfc,
                           const float* __restrict__ bfc,
                           float* __restrict__ out) {
    int gid = blockIdx.x * blockDim.x + threadIdx.x;
    int n = gid >> 5, lane = gid & 31;
    if (n >= N_NODES) return;
    const float* hp = h + (size_t)n * 128;
    float s = hp[lane]      * Wfc[lane]
            + hp[lane + 32] * Wfc[lane + 32]
            + hp[lane + 64] * Wfc[lane + 64]
            + hp[lane + 96] * Wfc[lane + 96];
#pragma unroll
    for (int o = 16; o > 0; o >>= 1) s += __shfl_down_sync(0xffffffffu, s, o);
    if (lane == 0) {
        float v = s + bfc[0];
        out[n] = 1.f / (1.f + __expf(-v));
    }
}

// ---------------- launch ----------------
extern "C" void kernel_launch(void* const* d_in, const int* in_sizes, int n_in,
                              void* d_out, int out_size) {
    const float* x      = (const float*)d_in[0];
    const int*   ei     = (const int*)  d_in[1];
    const float* W1     = (const float*)d_in[2];
    const float* a_src1 = (const float*)d_in[3];
    const float* a_dst1 = (const float*)d_in[4];
    const float* b1     = (const float*)d_in[5];
    const float* W2     = (const float*)d_in[6];
    const float* a_src2 = (const float*)d_in[7];
    const float* a_dst2 = (const float*)d_in[8];
    const float* b2     = (const float*)d_in[9];
    const float* Wfc    = (const float*)d_in[10];
    const float* bfc    = (const float*)d_in[11];
    float* out = (float*)d_out;

    int E  = in_sizes[1] / 2;
    int ET = E + N_NODES;

    float *h1, *agg1, *h2, *agg2, *ss, *sd, *z;
    cudaGetSymbolAddress((void**)&h1,   g_h1);
    cudaGetSymbolAddress((void**)&agg1, g_agg1);
    cudaGetSymbolAddress((void**)&h2,   g_h2);
    cudaGetSymbolAddress((void**)&agg2, g_agg2);
    cudaGetSymbolAddress((void**)&ss,   g_ss);
    cudaGetSymbolAddress((void**)&sd,   g_sd);
    cudaGetSymbolAddress((void**)&z,    g_z);

    const int TB = 256;

    // ===== layer 1 (H=4, F=256) =====
    gemm1_kernel<<<(N_NODES + 63) / 64, TB>>>(x, W1, h1);
    scores_kernel<H1><<<(N_NODES * H1 * 32 + TB - 1) / TB, TB>>>(h1, a_src1, a_dst1, ss, sd);
    cudaMemsetAsync(agg1, 0, (size_t)N_NODES * F1 * sizeof(float));
    cudaMemsetAsync(z,    0, (size_t)N_NODES * H1 * sizeof(float));
    edge_agg_kernel<H1, F1><<<(ET * 32 + TB - 1) / TB, TB>>>(ei, E, ET, ss, sd, z, h1, agg1);
    finalize_kernel<H1, F1><<<(N_NODES * F1 + TB - 1) / TB, TB>>>(agg1, z, b1);

    // ===== layer 2 (H=2, F=128) =====
    gemm2_tf32_kernel<<<(N_NODES + 127) / 128, TB>>>(agg1, W2, h2);
    scores_kernel<H2><<<(N_NODES * H2 * 32 + TB - 1) / TB, TB>>>(h2, a_src2, a_dst2, ss, sd);
    cudaMemsetAsync(agg2, 0, (size_t)N_NODES * F2 * sizeof(float));
    cudaMemsetAsync(z,    0, (size_t)N_NODES * H2 * sizeof(float));
    edge_agg_kernel<H2, F2><<<(ET * 32 + TB - 1) / TB, TB>>>(ei, E, ET, ss, sd, z, h2, agg2);
    finalize_kernel<H2, F2><<<(N_NODES * F2 + TB - 1) / TB, TB>>>(agg2, z, b2);

    // ===== final linear + sigmoid =====
    out_kernel<<<(N_NODES * 32 + TB - 1) / TB, TB>>>(agg2, Wfc, bfc, out);
}

// round 6
// speedup vs baseline: 1.4241x; 1.4241x over previous
#include <cuda_runtime.h>
#include <math.h>
#include <stdint.h>

#define N_NODES 50000
#define IN_DIM  27
#define F1      256
#define H1      4
#define F2      128
#define H2      2

// ---------------- scratch (no allocations allowed) ----------------
__device__ float g_h1  [N_NODES * F1];
__device__ float g_agg1[N_NODES * F1];
__device__ float g_h2  [N_NODES * F2];
__device__ float g_agg2[N_NODES * F2];
__device__ float g_ss  [N_NODES * H1];
__device__ float g_sd  [N_NODES * H1];
__device__ float g_z   [N_NODES * H1];

__device__ __forceinline__ void red_add_f4(float* p, float4 v) {
    asm volatile("red.global.add.v4.f32 [%0], {%1, %2, %3, %4};"
                 :: "l"(p), "f"(v.x), "f"(v.y), "f"(v.z), "f"(v.w) : "memory");
}

__device__ __forceinline__ float elu_fast(float v) {
    return (v > 0.f) ? v : (__expf(v) - 1.f);
}

// ---------------- GEMM1: x[N,27] @ W1[27,256] -> h1[N,256] ----------------
__global__ void gemm1_kernel(const float* __restrict__ x,
                             const float* __restrict__ W,
                             float* __restrict__ out) {
    __shared__ float Ws[IN_DIM * F1];
    __shared__ float xs[64 * IN_DIM];
    int t = threadIdx.x;                // 256 threads
    for (int i = t; i < IN_DIM * F1; i += 256) Ws[i] = W[i];
    int r0 = blockIdx.x * 64;
    for (int i = t; i < 64 * IN_DIM; i += 256) {
        int r = i / IN_DIM, c = i % IN_DIM;
        int gr = r0 + r;
        xs[i] = (gr < N_NODES) ? x[gr * IN_DIM + c] : 0.f;
    }
    __syncthreads();
    float w[IN_DIM];
#pragma unroll
    for (int k = 0; k < IN_DIM; k++) w[k] = Ws[k * F1 + t];
    for (int r = 0; r < 64; r++) {
        int gr = r0 + r;
        if (gr >= N_NODES) break;
        float acc = 0.f;
#pragma unroll
        for (int k = 0; k < IN_DIM; k++) acc += xs[r * IN_DIM + k] * w[k];
        out[(size_t)gr * F1 + t] = acc;
    }
}

// ---------------- per-node attention half-scores ----------------
template<int H>
__global__ void scores_kernel(const float* __restrict__ h,
                              const float* __restrict__ asrc,
                              const float* __restrict__ adst,
                              float* __restrict__ ss, float* __restrict__ sd) {
    int gid  = blockIdx.x * blockDim.x + threadIdx.x;
    int warp = gid >> 5, lane = gid & 31;
    if (warp >= N_NODES * H) return;
    int n = warp / H, hh = warp % H;
    const float* hp = h + (size_t)n * (H * 64) + hh * 64;
    const float* as = asrc + hh * 64;
    const float* ad = adst + hh * 64;
    float v0 = hp[lane], v1 = hp[lane + 32];
    float s1 = v0 * as[lane] + v1 * as[lane + 32];
    float s2 = v0 * ad[lane] + v1 * ad[lane + 32];
#pragma unroll
    for (int o = 16; o > 0; o >>= 1) {
        s1 += __shfl_down_sync(0xffffffffu, s1, o);
        s2 += __shfl_down_sync(0xffffffffu, s2, o);
    }
    if (lane == 0) { ss[warp] = s1; sd[warp] = s2; }
}

// ---------------- edge pass: z += e ; agg += e * h[src] (no max subtraction;
// softmax is shift-invariant and logits are bounded) ----------------
template<int H, int F>
__global__ void edge_agg_kernel(const int* __restrict__ ei, int E, int ET,
                                const float* __restrict__ ss,
                                const float* __restrict__ sd,
                                float* __restrict__ z,
                                const float* __restrict__ h,
                                float* __restrict__ agg) {
    int gid = blockIdx.x * blockDim.x + threadIdx.x;
    int e = gid >> 5, lane = gid & 31;
    if (e >= ET) return;
    int src, dst;
    if (e < E) { src = ei[e]; dst = ei[E + e]; }
    else       { src = dst = e - E; }
    float ev = 0.f;
    if (lane < H) {
        float l = ss[src * H + lane] + sd[dst * H + lane];
        l = (l > 0.f) ? l : 0.2f * l;
        ev = __expf(l);
        atomicAdd(&z[dst * H + lane], ev);
    }
    const float4* hs = (const float4*)(h + (size_t)src * F);
    float* ag = agg + (size_t)dst * F;
#pragma unroll
    for (int i = 0; i < F / 128; i++) {
        int f = lane + i * 32;                            // float4 index; col = 4f
        float evc = __shfl_sync(0xffffffffu, ev, f >> 4); // head = 4f/64 = f>>4
        float4 v = hs[f];
        v.x *= evc; v.y *= evc; v.z *= evc; v.w *= evc;
        red_add_f4(ag + f * 4, v);
    }
}

// ---------------- GEMM2 (fp32 SIMT) with FUSED layer-1 finalize on A-load:
// A_eff[r][c] = elu(agg1[r][c] / (z1[r,head(c)] + eps) + b1[c])
// C = A_eff @ B ; 128x128 block tile, 256 threads, 8x8 per thread ----------------
__global__ void gemm2_fused_kernel(const float* __restrict__ A,
                                   const float* __restrict__ zA,
                                   const float* __restrict__ bA,
                                   const float* __restrict__ B,
                                   float* __restrict__ C) {
    __shared__ float As[16][132];   // transposed: As[k][m]
    __shared__ float Bs[16][128];
    int t = threadIdx.x;            // 256 threads
    int tx = t & 15, ty = t >> 4;
    int row0 = blockIdx.x * 128;
    float acc[8][8];
#pragma unroll
    for (int i = 0; i < 8; i++)
#pragma unroll
        for (int j = 0; j < 8; j++) acc[i][j] = 0.f;

    for (int kt = 0; kt < 256; kt += 16) {
#pragma unroll
        for (int s = 0; s < 2; s++) {
            int i = t + s * 256;     // [0,512): 128 rows x 4 k-quads
            int r = i >> 2, kq = i & 3;
            int gr = row0 + r;
            float4 v = make_float4(0.f, 0.f, 0.f, 0.f);
            if (gr < N_NODES) {
                int c = kt + kq * 4;            // 4-aligned, never crosses 64
                int hh = c >> 6;
                v = *(const float4*)&A[(size_t)gr * 256 + c];
                float rz = __fdividef(1.f, zA[gr * H1 + hh] + 1e-16f);
                float4 bb = *(const float4*)&bA[c];
                v.x = elu_fast(fmaf(v.x, rz, bb.x));
                v.y = elu_fast(fmaf(v.y, rz, bb.y));
                v.z = elu_fast(fmaf(v.z, rz, bb.z));
                v.w = elu_fast(fmaf(v.w, rz, bb.w));
            }
            As[kq * 4 + 0][r] = v.x;
            As[kq * 4 + 1][r] = v.y;
            As[kq * 4 + 2][r] = v.z;
            As[kq * 4 + 3][r] = v.w;
        }
#pragma unroll
        for (int s = 0; s < 2; s++) {
            int i = t + s * 256;     // [0,512): 16 k x 32 col-quads
            int k = i >> 5, c = i & 31;
            *(float4*)&Bs[k][c * 4] = *(const float4*)&B[(size_t)(kt + k) * 128 + c * 4];
        }
        __syncthreads();
#pragma unroll
        for (int k = 0; k < 16; k++) {
            float a[8], bb[8];
            *(float4*)&a[0]  = *(float4*)&As[k][ty * 8];
            *(float4*)&a[4]  = *(float4*)&As[k][ty * 8 + 4];
            *(float4*)&bb[0] = *(float4*)&Bs[k][tx * 8];
            *(float4*)&bb[4] = *(float4*)&Bs[k][tx * 8 + 4];
#pragma unroll
            for (int i = 0; i < 8; i++)
#pragma unroll
                for (int j = 0; j < 8; j++)
                    acc[i][j] += a[i] * bb[j];
        }
        __syncthreads();
    }
#pragma unroll
    for (int i = 0; i < 8; i++) {
        int gr = row0 + ty * 8 + i;
        if (gr >= N_NODES) continue;
        *(float4*)&C[(size_t)gr * 128 + tx * 8] =
            make_float4(acc[i][0], acc[i][1], acc[i][2], acc[i][3]);
        *(float4*)&C[(size_t)gr * 128 + tx * 8 + 4] =
            make_float4(acc[i][4], acc[i][5], acc[i][6], acc[i][7]);
    }
}

// ---------------- final (FUSED layer-2 finalize):
// out = sigmoid( elu(agg2/(z2+eps)+b2) @ Wfc + bfc ) ----------------
__global__ void out_fused_kernel(const float* __restrict__ agg,
                                 const float* __restrict__ z,
                                 const float* __restrict__ b,
                                 const float* __restrict__ Wfc,
                                 const float* __restrict__ bfc,
                                 float* __restrict__ out) {
    int gid = blockIdx.x * blockDim.x + threadIdx.x;
    int n = gid >> 5, lane = gid & 31;
    if (n >= N_NODES) return;
    const float* hp = agg + (size_t)n * 128;
    float rz0 = __fdividef(1.f, z[n * H2 + 0] + 1e-16f);
    float rz1 = __fdividef(1.f, z[n * H2 + 1] + 1e-16f);
    float v0 = elu_fast(fmaf(hp[lane],      rz0, b[lane]));
    float v1 = elu_fast(fmaf(hp[lane + 32], rz0, b[lane + 32]));
    float v2 = elu_fast(fmaf(hp[lane + 64], rz1, b[lane + 64]));
    float v3 = elu_fast(fmaf(hp[lane + 96], rz1, b[lane + 96]));
    float s = v0 * Wfc[lane] + v1 * Wfc[lane + 32]
            + v2 * Wfc[lane + 64] + v3 * Wfc[lane + 96];
#pragma unroll
    for (int o = 16; o > 0; o >>= 1) s += __shfl_down_sync(0xffffffffu, s, o);
    if (lane == 0) {
        float v = s + bfc[0];
        out[n] = 1.f / (1.f + __expf(-v));
    }
}

// ---------------- launch ----------------
extern "C" void kernel_launch(void* const* d_in, const int* in_sizes, int n_in,
                              void* d_out, int out_size) {
    const float* x      = (const float*)d_in[0];
    const int*   ei     = (const int*)  d_in[1];
    const float* W1     = (const float*)d_in[2];
    const float* a_src1 = (const float*)d_in[3];
    const float* a_dst1 = (const float*)d_in[4];
    const float* b1     = (const float*)d_in[5];
    const float* W2     = (const float*)d_in[6];
    const float* a_src2 = (const float*)d_in[7];
    const float* a_dst2 = (const float*)d_in[8];
    const float* b2     = (const float*)d_in[9];
    const float* Wfc    = (const float*)d_in[10];
    const float* bfc    = (const float*)d_in[11];
    float* out = (float*)d_out;

    int E  = in_sizes[1] / 2;
    int ET = E + N_NODES;

    float *h1, *agg1, *h2, *agg2, *ss, *sd, *z;
    cudaGetSymbolAddress((void**)&h1,   g_h1);
    cudaGetSymbolAddress((void**)&agg1, g_agg1);
    cudaGetSymbolAddress((void**)&h2,   g_h2);
    cudaGetSymbolAddress((void**)&agg2, g_agg2);
    cudaGetSymbolAddress((void**)&ss,   g_ss);
    cudaGetSymbolAddress((void**)&sd,   g_sd);
    cudaGetSymbolAddress((void**)&z,    g_z);

    const int TB = 256;

    // ===== layer 1 (H=4, F=256) =====
    gemm1_kernel<<<(N_NODES + 63) / 64, TB>>>(x, W1, h1);
    scores_kernel<H1><<<(N_NODES * H1 * 32 + TB - 1) / TB, TB>>>(h1, a_src1, a_dst1, ss, sd);
    cudaMemsetAsync(agg1, 0, (size_t)N_NODES * F1 * sizeof(float));
    cudaMemsetAsync(z,    0, (size_t)N_NODES * H1 * sizeof(float));
    edge_agg_kernel<H1, F1><<<(ET * 32 + TB - 1) / TB, TB>>>(ei, E, ET, ss, sd, z, h1, agg1);

    // ===== layer 2 (H=2, F=128): gemm2 fuses layer-1 normalize+bias+elu =====
    gemm2_fused_kernel<<<(N_NODES + 127) / 128, TB>>>(agg1, z, b1, W2, h2);
    scores_kernel<H2><<<(N_NODES * H2 * 32 + TB - 1) / TB, TB>>>(h2, a_src2, a_dst2, ss, sd);
    cudaMemsetAsync(agg2, 0, (size_t)N_NODES * F2 * sizeof(float));
    cudaMemsetAsync(z,    0, (size_t)N_NODES * H2 * sizeof(float));
    edge_agg_kernel<H2, F2><<<(ET * 32 + TB - 1) / TB, TB>>>(ei, E, ET, ss, sd, z, h2, agg2);

    // ===== final: fuses layer-2 normalize+bias+elu with the 128->1 dot =====
    out_fused_kernel<<<(N_NODES * 32 + TB - 1) / TB, TB>>>(agg2, z, b2, Wfc, bfc, out);
}